// round 16
// baseline (speedup 1.0000x reference)
#include <cuda_runtime.h>
#include <cstdint>
#include <math.h>

#define BATCH 64
#define SEQ   2048
#define INP   256
#define HID   512
#define NCTA  128     // 16 clusters x 8 ranks
#define THR   512
#define CLU   8       // ranks per cluster (one batch group)
#define BGR   4       // batches per group
#define JGR   64      // hidden columns per CTA (rank)

// ---------------- packed fp32x2 FMA helpers (FFMA2) ----------------
__device__ __forceinline__ void fma2(unsigned long long &d, unsigned long long a, unsigned long long b) {
    asm("fma.rn.f32x2 %0, %1, %2, %0;" : "+l"(d) : "l"(a), "l"(b));
}
__device__ __forceinline__ unsigned long long pack2(float lo, float hi) {
    unsigned long long r;
    asm("mov.b64 %0, {%1, %2};" : "=l"(r) : "f"(lo), "f"(hi));
    return r;
}
__device__ __forceinline__ float lo2(unsigned long long v) { return __uint_as_float((unsigned)v); }
__device__ __forceinline__ float hi2(unsigned long long v) { return __uint_as_float((unsigned)(v >> 32)); }

// ---------------- smem / cluster helpers ----------------
__device__ __forceinline__ uint32_t smem_u32(const void* p) {
    uint32_t a;
    asm("{ .reg .u64 t; cvta.to.shared.u64 t, %1; cvt.u32.u64 %0, t; }" : "=r"(a) : "l"(p));
    return a;
}
__device__ __forceinline__ uint32_t my_rank() {
    uint32_t r; asm("mov.u32 %0, %%cluster_ctarank;" : "=r"(r)); return r;
}
__device__ __forceinline__ uint32_t mapa_u32(uint32_t laddr, uint32_t rank) {
    uint32_t r;
    asm("mapa.shared::cluster.u32 %0, %1, %2;" : "=r"(r) : "r"(laddr), "r"(rank));
    return r;
}
__device__ __forceinline__ void mbar_init(uint32_t a, uint32_t cnt) {
    asm volatile("mbarrier.init.shared.b64 [%0], %1;" :: "r"(a), "r"(cnt) : "memory");
}
__device__ __forceinline__ void mbar_inval(uint32_t a) {
    asm volatile("mbarrier.inval.shared.b64 [%0];" :: "r"(a) : "memory");
}
__device__ __forceinline__ void mbar_expect_tx(uint32_t a, uint32_t tx) {
    asm volatile("mbarrier.arrive.expect_tx.shared.b64 _, [%0], %1;" :: "r"(a), "r"(tx) : "memory");
}
__device__ __forceinline__ void mbar_wait_parity(uint32_t mb, uint32_t ph) {
    uint32_t done;
    do {
        asm volatile(
            "{\n\t.reg .pred p;\n\t"
            "mbarrier.try_wait.parity.acquire.cta.shared::cta.b64 p, [%1], %2, 0x989680;\n\t"
            "selp.b32 %0,1,0,p;\n\t}"
            : "=r"(done) : "r"(mb), "r"(ph) : "memory");
    } while (!done);
}
// SMEM(cta) -> SMEM(cluster peer) bulk copy, completing on the PEER's mbarrier.
__device__ __forceinline__ void bulk_s2s(uint32_t dst_remote, uint32_t src_local,
                                         uint32_t bytes, uint32_t rmbar) {
    asm volatile(
        "cp.async.bulk.shared::cluster.shared::cta.mbarrier::complete_tx::bytes "
        "[%0], [%1], %2, [%3];"
        :: "r"(dst_remote), "r"(src_local), "r"(bytes), "r"(rmbar) : "memory");
}
#define FENCE_PROXY_ASYNC() asm volatile("fence.proxy.async.shared::cta;" ::: "memory")
#define CLUSTER_SYNC() do {                                          \
    asm volatile("barrier.cluster.arrive.aligned;" ::: "memory");    \
    asm volatile("barrier.cluster.wait.aligned;" ::: "memory");      \
} while (0)

// ---------------- cp.async (X prefetch) ----------------
__device__ __forceinline__ void cpasync16(uint32_t dst, const void* src) {
    asm volatile("cp.async.cg.shared.global [%0], [%1], 16;" :: "r"(dst), "l"(src));
}
#define CP_COMMIT() asm volatile("cp.async.commit_group;" ::: "memory")
#define CP_WAIT1()  asm volatile("cp.async.wait_group 1;" ::: "memory")

// 4-stage butterfly over a[16] + xor-1 fold (verified mapping):
// afterwards EVEN lane L holds output o=(L>>1)&15: b=(L>>3)&3, jl=(L>>1)&3.
#define BFLY16(a, lane)                                                     \
    do {                                                                    \
        _Pragma("unroll")                                                   \
        for (int off = 16, nk = 8; off >= 2; off >>= 1, nk >>= 1) {         \
            const bool up = ((lane) & off) != 0;                            \
            _Pragma("unroll")                                               \
            for (int i = 0; i < nk; i++) {                                  \
                float send = up ? (a)[i] : (a)[i + nk];                     \
                float recv = __shfl_xor_sync(0xffffffffu, send, off);       \
                (a)[i] = (up ? (a)[i + nk] : (a)[i]) + recv;                \
            }                                                               \
        }                                                                   \
        (a)[0] += __shfl_xor_sync(0xffffffffu, (a)[0], 1);                  \
    } while (0)

// =====================================================================
// ONE persistent kernel. 16 independent clusters of 8 CTAs; cluster =
// one batch group (4 batches), rank r owns hidden cols r*64..r*64+63.
// Each CTA holds the FULL group h (4x512, double-buffered) in SMEM.
// Per step: compute 4b x 64j slice (16 warps, warp = 4b x 4j, U+W in
// regs, FFMA2 + butterfly) -> stage slice in houtsh -> bar -> warp0
// bulk-copies 4x256B to every rank's hsh[(s+1)&1], completing on the
// remote mbarrier (tx bytes). Consumer: ONE parity try_wait (acquire.cta,
// HW sleep) and h is already local. No flags, no polls, no h LDG/STG.
// 2-ahead overwrite impossible: a producer's wait(s) completes only
// after every peer's step-(s) push, which follows all that peer's reads
// of the buffer being overwritten (reads precede its bar3+bulks).
// Fully self-contained: no __device__ state -> trivially replay-safe.
// =====================================================================
__global__ __launch_bounds__(THR, 1) __cluster_dims__(CLU, 1, 1)
void fused_kernel(const float* __restrict__ x,  const float* __restrict__ Ww,
                  const float* __restrict__ Wb, const float* __restrict__ Uw,
                  const float* __restrict__ Ub, const float* __restrict__ Vw,
                  const float* __restrict__ Vb, float* __restrict__ out) {
    __shared__ __align__(16) float   Xsh[2][BGR * INP];     // 8 KB
    __shared__ __align__(16) float   hsh[2][BGR * HID];     // 16 KB (full group h)
    __shared__ __align__(16) float   houtsh[2][BGR * JGR];  // 2 KB (own slice staging)
    __shared__ __align__(8)  unsigned long long mbar_sto;

    const int t    = threadIdx.x;
    const int g    = blockIdx.x >> 3;       // batch group 0..15
    const uint32_t r = my_rank();           // 0..7
    const int b0   = g * BGR;
    const int j0g  = (int)r * JGR;          // global col base of this CTA
    const int w    = t >> 5;                // 0..15
    const int lane = t & 31;
    const int wj   = w;                     // warp w -> local cols w*4..+3

    // writer mapping: even lane L -> o=(L>>1): b=(L>>3)&3, jl=(L>>1)&3
    const int ob  = (lane >> 3) & 3;
    const int ojl = (lane >> 1) & 3;
    const bool writer = ((lane & 1) == 0);
    const int jloc = wj * 4 + ojl;          // 0..63
    const int jabs = j0g + jloc;            // global hidden col

    const uint32_t mbar = smem_u32(&mbar_sto);

    // ---- init mbarrier, make visible cluster-wide, open phase 0 ----
    if (t == 0) mbar_init(mbar, 1);
    __syncthreads();
    CLUSTER_SYNC();
    if (t == 0) mbar_expect_tx(mbar, 8192);   // phase 0 expects full 8KB of h(1)

    // ---- zero local h buffer 0 (h(0) = 0) ----
#pragma unroll
    for (int i = t; i < BGR * HID; i += THR) hsh[0][i] = 0.0f;

    // ---- one-time: U slice (4 quads) + W slice (2 quads) into registers ----
    ulonglong2 ureg[4][4], wreg[2][4];
#pragma unroll
    for (int qi = 0; qi < 4; qi++) {
        const int kb = qi * 128 + lane * 4;
#pragma unroll
        for (int j = 0; j < 4; j++) {
            const float* up = Uw + (size_t)kb * HID + (j0g + wj * 4 + j);
            ureg[qi][j].x = pack2(up[0], up[HID]);
            ureg[qi][j].y = pack2(up[2 * HID], up[3 * HID]);
        }
    }
#pragma unroll
    for (int qi = 0; qi < 2; qi++) {
        const int kb = qi * 128 + lane * 4;
#pragma unroll
        for (int j = 0; j < 4; j++) {
            const float* wp = Ww + (size_t)kb * HID + (j0g + wj * 4 + j);
            wreg[qi][j].x = pack2(wp[0], wp[HID]);
            wreg[qi][j].y = pack2(wp[2 * HID], wp[3 * HID]);
        }
    }
    const float ubj = Ub[jabs];
    const float wbj = Wb[jabs];

    // ---- per-lane bulk-push descriptors (warp 0, lane = target rank) ----
    uint32_t rm_mbar = 0, rdst0 = 0, rdst1 = 0;
    if (w == 0 && lane < CLU) {
        rm_mbar = mapa_u32(mbar, (uint32_t)lane);
        // dst col-offset = MY rank slice (r*256B) within target's hsh row
        rdst0 = mapa_u32(smem_u32(&hsh[0][0]) + (uint32_t)r * 256u, (uint32_t)lane);
        rdst1 = mapa_u32(smem_u32(&hsh[1][0]) + (uint32_t)r * 256u, (uint32_t)lane);
    }

    // ---- X staging: threads t<256 copy one 16B chunk (4 rows x 64 f4) ----
    const int xr = (t >> 6) & 3;
    const int xc = t & 63;
    const float* const xsrc = x + ((size_t)(b0 + xr) * SEQ) * INP + xc * 4;
    const uint32_t xdst0 = smem_u32(&Xsh[0][xr * INP + xc * 4]);
    const uint32_t xdst1 = smem_u32(&Xsh[1][xr * INP + xc * 4]);
#define STAGE_X(sp) do { if (t < 256) cpasync16(((sp) & 1) ? xdst1 : xdst0, xsrc + (size_t)(sp) * INP); } while (0)

    // wx for step sp from Xsh[sp&1] + wreg; valid on even lanes
#define WX_COMPUTE(sp, dst)                                                             \
    do {                                                                                \
        unsigned long long wacc[16];                                                    \
        _Pragma("unroll")                                                               \
        for (int o = 0; o < 16; o++) wacc[o] = 0ull;                                    \
        const float* xb = Xsh[(sp) & 1];                                                \
        _Pragma("unroll")                                                               \
        for (int qi = 0; qi < 2; qi++) {                                                \
            const int kb = qi * 128 + lane * 4;                                         \
            ulonglong2 xq[4];                                                           \
            _Pragma("unroll")                                                           \
            for (int b = 0; b < 4; b++)                                                 \
                xq[b] = *(const ulonglong2*)(xb + b * INP + kb);                        \
            _Pragma("unroll")                                                           \
            for (int b = 0; b < 4; b++)                                                 \
                _Pragma("unroll")                                                       \
                for (int j = 0; j < 4; j++) {                                           \
                    fma2(wacc[b * 4 + j], xq[b].x, wreg[qi][j].x);                      \
                    fma2(wacc[b * 4 + j], xq[b].y, wreg[qi][j].y);                      \
                }                                                                       \
        }                                                                               \
        float vv[16];                                                                   \
        _Pragma("unroll")                                                               \
        for (int o = 0; o < 16; o++) vv[o] = lo2(wacc[o]) + hi2(wacc[o]);               \
        BFLY16(vv, lane);                                                               \
        (dst) = vv[0] + wbj;                                                            \
    } while (0)

    // ---- prologue: X(0), X(1); wx(0) ----
    STAGE_X(0); CP_COMMIT();
    STAGE_X(1); CP_COMMIT();
    CP_WAIT1();
    __syncthreads();                 // X(0) + hsh[0] zero visible
    float wx_cur;
    WX_COMPUTE(0, wx_cur);

    for (int s = 0; s < SEQ; s++) {
        // 1. prefetch X(s+2); ensure X(s+1) visible CTA-wide
        if (s + 2 < SEQ) STAGE_X(s + 2);
        CP_COMMIT();
        CP_WAIT1();
        __syncthreads();             // bar1

        // 2. wx(s+1) from Xsh (independent of h) — hides the h wait below
        float wx_next = 0.0f;
        if (s + 1 < SEQ) WX_COMPUTE(s + 1, wx_next);

        // 3. wait for h(s) delivery (phase s-1), open next phase
        if (s > 0) {
            mbar_wait_parity(mbar, (unsigned)((s - 1) & 1));
            if (t == 0) mbar_expect_tx(mbar, 8192);   // phase s (h(s+1))
        }

        // 4. scan compute: 4b x 4j FFMA2 tile from local hsh[s&1]
        const float* hb = hsh[s & 1];
        unsigned long long acc[16];
#pragma unroll
        for (int o = 0; o < 16; o++) acc[o] = 0ull;
#pragma unroll
        for (int qi = 0; qi < 4; qi++) {
            const int kb = qi * 128 + lane * 4;
            ulonglong2 hq[4];
#pragma unroll
            for (int b = 0; b < 4; b++)
                hq[b] = *(const ulonglong2*)(hb + b * HID + kb);
#pragma unroll
            for (int b = 0; b < 4; b++)
#pragma unroll
                for (int j = 0; j < 4; j++) {
                    fma2(acc[b * 4 + j], hq[b].x, ureg[qi][j].x);
                    fma2(acc[b * 4 + j], hq[b].y, ureg[qi][j].y);
                }
        }
        float v[16];
#pragma unroll
        for (int o = 0; o < 16; o++) v[o] = lo2(acc[o]) + hi2(acc[o]);
        BFLY16(v, lane);

        const int nb = (s + 1) & 1;
        if (writer) {
            float hnew = tanhf(wx_cur + ubj + v[0]);
            houtsh[nb][ob * JGR + jloc] = hnew;
        }

        // 5. publish: bar orders all reads+STS; async-proxy fence; bulk push
        __syncthreads();             // bar3
        if (w == 0) {
            FENCE_PROXY_ASYNC();
            if (lane < CLU) {
                const uint32_t src = smem_u32(&houtsh[nb][0]);
                const uint32_t dst = nb ? rdst1 : rdst0;
#pragma unroll
                for (int b = 0; b < 4; b++)
                    bulk_s2s(dst + (uint32_t)b * 2048u, src + (uint32_t)b * 256u,
                             256u, rm_mbar);
            }
        }
        wx_cur = wx_next;
    }

    // ---- final phase: h(SEQ) lands in hsh[0] of EVERY rank ----
    mbar_wait_parity(mbar, (unsigned)((SEQ - 1) & 1));
    __syncthreads();

    // ---- readout (rank 0 only): out = sigmoid(h_T @ V + Vb) ----
    if (r == 0 && w < 8) {
        const int b = w >> 1, o = w & 1;
        float p = 0.0f;
        for (int j = lane; j < HID; j += 32)
            p += hsh[0][b * HID + j] * Vw[(size_t)j * 2 + o];
#pragma unroll
        for (int off = 16; off > 0; off >>= 1)
            p += __shfl_down_sync(0xffffffffu, p, off);
        if (lane == 0)
            out[(size_t)(b0 + b) * 2 + o] = 1.0f / (1.0f + expf(-(p + Vb[o])));
    }

    // ---- cleanup: no rank exits while peers' bulks/mbar ops may target it ----
    __syncthreads();
    if (t == 0) mbar_inval(mbar);
    CLUSTER_SYNC();
}

// =====================================================================
extern "C" void kernel_launch(void* const* d_in, const int* in_sizes, int n_in,
                              void* d_out, int out_size) {
    const float* x  = (const float*)d_in[0];
    const float* Ww = (const float*)d_in[1];
    const float* Wb = (const float*)d_in[2];
    const float* Uw = (const float*)d_in[3];
    const float* Ub = (const float*)d_in[4];
    const float* Vw = (const float*)d_in[5];
    const float* Vb = (const float*)d_in[6];
    float* out = (float*)d_out;

    fused_kernel<<<NCTA, THR>>>(x, Ww, Wb, Uw, Ub, Vw, Vb, out);
}

// round 17
// speedup vs baseline: 1.9164x; 1.9164x over previous
#include <cuda_runtime.h>
#include <cstdint>
#include <math.h>

#define BATCH 64
#define SEQ   2048
#define INP   256
#define HID   512
#define NCTA  128    // 8 p-slots x 16 jg slices; each CTA runs TWO chains
#define THR   512
#define BGR   4      // batches per chain
#define JGR   32     // hidden columns per CTA

// ---------------- scratch (no allocations allowed) ----------------
__device__ float    g_hbuf[2 * BATCH * HID];     // double-buffered hidden state
__device__ float    g_opart[16 * 16 * 8];        // per (group, jg) readout partials
__device__ unsigned g_flags[16 * 16];            // per (group, jg) epoch flags

// ---------------- packed fp32x2 FMA helpers (FFMA2) ----------------
__device__ __forceinline__ void fma2(unsigned long long &d, unsigned long long a, unsigned long long b) {
    asm("fma.rn.f32x2 %0, %1, %2, %0;" : "+l"(d) : "l"(a), "l"(b));
}
__device__ __forceinline__ unsigned long long pack2(float lo, float hi) {
    unsigned long long r;
    asm("mov.b64 %0, {%1, %2};" : "=l"(r) : "f"(lo), "f"(hi));
    return r;
}
__device__ __forceinline__ float lo2(unsigned long long v) { return __uint_as_float((unsigned)v); }
__device__ __forceinline__ float hi2(unsigned long long v) { return __uint_as_float((unsigned)(v >> 32)); }

// ---------------- sync ops (no scope>=cluster fences in step path) ----------------
__device__ __forceinline__ unsigned ldacq(const unsigned* p) {
    unsigned v;
    asm volatile("ld.acquire.gpu.global.u32 %0, [%1];" : "=r"(v) : "l"(p) : "memory");
    return v;
}
__device__ __forceinline__ void strel(unsigned* p, unsigned v) {
    asm volatile("st.release.gpu.global.u32 [%0], %1;" :: "l"(p), "r"(v) : "memory");
}

// ---------------- named barriers (per-chain; chains never couple) ----------------
#define BAR_C(c)  asm volatile("bar.sync %0, 256;" :: "r"((c) + 1) : "memory")
#define BAR_ALL() asm volatile("bar.sync 3, 512;" ::: "memory")

// ---------------- cp.async ----------------
__device__ __forceinline__ uint32_t smem_u32(const void* p) {
    uint32_t a;
    asm("{ .reg .u64 t; cvta.to.shared.u64 t, %1; cvt.u32.u64 %0, t; }" : "=r"(a) : "l"(p));
    return a;
}
__device__ __forceinline__ void cpasync16(uint32_t dst, const void* src) {
    asm volatile("cp.async.cg.shared.global [%0], [%1], 16;" :: "r"(dst), "l"(src));
}
#define CP_COMMIT() asm volatile("cp.async.commit_group;" ::: "memory")
#define CP_WAIT1()  asm volatile("cp.async.wait_group 1;" ::: "memory")

// 4-stage butterfly over a[16] + xor-1 fold (verified mapping):
// afterwards EVEN lane L holds output o=(L>>1)&15: b=(L>>3)&3, jl=(L>>1)&3.
#define BFLY16(a, lane)                                                     \
    do {                                                                    \
        _Pragma("unroll")                                                   \
        for (int off = 16, nk = 8; off >= 2; off >>= 1, nk >>= 1) {         \
            const bool up = ((lane) & off) != 0;                            \
            _Pragma("unroll")                                               \
            for (int i = 0; i < nk; i++) {                                  \
                float send = up ? (a)[i] : (a)[i + nk];                     \
                float recv = __shfl_xor_sync(0xffffffffu, send, off);       \
                (a)[i] = (up ? (a)[i + nk] : (a)[i]) + recv;                \
            }                                                               \
        }                                                                   \
        (a)[0] += __shfl_xor_sync(0xffffffffu, (a)[0], 1);                  \
    } while (0)

// =====================================================================
// ONE persistent kernel, 128 CTAs x 512 threads. cta = p*16 + jg.
// TWO independent chains per CTA: chain c (warps c*8..c*8+7) runs batch
// group g = p*2+c (4 batches) x hidden cols jg*32..+31. Chains use
// named barriers (id c+1) and separate flags/smem, so when one chain's
// warps park in poll/barrier, the other's warps fill the SMSP issue
// slots (2 warps of each chain per SMSP). A one-time bar.sync 3,512
// staggers chain B by one full A-step to force anti-phase.
// Per chain: U (4 quads) + W (2 quads) in registers; wx pipelined one
// step ahead (cp.async X two ahead) and computed while the chain's
// warp0 acquire-polls its group's 16 packed flags; h via L2 (R11-proven
// path); fused readout with epoch SEQ+1.
// =====================================================================
__global__ __launch_bounds__(THR, 1)
void fused_kernel(const float* __restrict__ x,  const float* __restrict__ Ww,
                  const float* __restrict__ Wb, const float* __restrict__ Uw,
                  const float* __restrict__ Ub, const float* __restrict__ Vw,
                  const float* __restrict__ Vb, float* __restrict__ out) {
    __shared__ __align__(16) float Xsh[2][2][BGR * INP];   // [chain][buf] 8 KB
    __shared__ __align__(16) float hsh[2][BGR * HID];      // [chain] 16 KB

    const int t    = threadIdx.x;
    const int cta  = blockIdx.x;
    const int p    = cta >> 4;            // 0..7
    const int jg   = cta & 15;
    const int w    = t >> 5;              // 0..15
    const int lane = t & 31;
    const int c    = w >> 3;              // chain 0/1
    const int wc   = w & 7;               // warp-in-chain; cols wc*4..+3
    const int tc   = t & 255;             // thread-in-chain
    const int g    = p * 2 + c;           // batch group 0..15
    const int b0   = g * BGR;
    const int j0   = jg * JGR;

    // writer mapping: even lane L -> o=(L>>1): b=(L>>3)&3, jl=(L>>1)&3
    const int ob  = (lane >> 3) & 3;
    const int ojl = (lane >> 1) & 3;
    const bool writer = ((lane & 1) == 0);
    const int babs = b0 + ob;
    const int jabs = j0 + wc * 4 + ojl;

    unsigned* const fgrp = g_flags + g * 16;
    const unsigned base = fgrp[jg];       // replay-safe epoch base (per chain)

    // ---- one-time: U slice (4 quads) + W slice (2 quads) into registers ----
    ulonglong2 ureg[4][4], wreg[2][4];
#pragma unroll
    for (int qi = 0; qi < 4; qi++) {
        const int kb = qi * 128 + lane * 4;
#pragma unroll
        for (int j = 0; j < 4; j++) {
            const float* up = Uw + (size_t)kb * HID + (j0 + wc * 4 + j);
            ureg[qi][j].x = pack2(up[0], up[HID]);
            ureg[qi][j].y = pack2(up[2 * HID], up[3 * HID]);
        }
    }
#pragma unroll
    for (int qi = 0; qi < 2; qi++) {
        const int kb = qi * 128 + lane * 4;
#pragma unroll
        for (int j = 0; j < 4; j++) {
            const float* wp = Ww + (size_t)kb * HID + (j0 + wc * 4 + j);
            wreg[qi][j].x = pack2(wp[0], wp[HID]);
            wreg[qi][j].y = pack2(wp[2 * HID], wp[3 * HID]);
        }
    }
    const float ubj = Ub[jabs];
    const float wbj = Wb[jabs];

    // ---- X staging: chain thread tc copies one 16B chunk (256 x 16B = 4KB) ----
    const int xr = tc >> 6;               // batch row 0..3
    const int xc = tc & 63;               // float4 col 0..63
    const float* const xsrc = x + ((size_t)(b0 + xr) * SEQ) * INP + xc * 4;
    const uint32_t xdst0 = smem_u32(&Xsh[c][0][xr * INP + xc * 4]);
    const uint32_t xdst1 = smem_u32(&Xsh[c][1][xr * INP + xc * 4]);
#define STAGE_X(sp) cpasync16(((sp) & 1) ? xdst1 : xdst0, xsrc + (size_t)(sp) * INP)

    float* const hshc = hsh[c];

    // wx for step sp from Xsh[c][sp&1] + wreg; valid on even lanes
#define WX_COMPUTE(sp, dst)                                                             \
    do {                                                                                \
        unsigned long long wacc[16];                                                    \
        _Pragma("unroll")                                                               \
        for (int o = 0; o < 16; o++) wacc[o] = 0ull;                                    \
        const float* xb = Xsh[c][(sp) & 1];                                             \
        _Pragma("unroll")                                                               \
        for (int qi = 0; qi < 2; qi++) {                                                \
            const int kb = qi * 128 + lane * 4;                                         \
            ulonglong2 xq[4];                                                           \
            _Pragma("unroll")                                                           \
            for (int b = 0; b < 4; b++)                                                 \
                xq[b] = *(const ulonglong2*)(xb + b * INP + kb);                        \
            _Pragma("unroll")                                                           \
            for (int b = 0; b < 4; b++)                                                 \
                _Pragma("unroll")                                                       \
                for (int j = 0; j < 4; j++) {                                           \
                    fma2(wacc[b * 4 + j], xq[b].x, wreg[qi][j].x);                      \
                    fma2(wacc[b * 4 + j], xq[b].y, wreg[qi][j].y);                      \
                }                                                                       \
        }                                                                               \
        float vv[16];                                                                   \
        _Pragma("unroll")                                                               \
        for (int o = 0; o < 16; o++) vv[o] = lo2(wacc[o]) + hi2(wacc[o]);               \
        BFLY16(vv, lane);                                                               \
        (dst) = vv[0] + wbj;                                                            \
    } while (0)

    // ---- prologue: X(0), X(1); wx(0) ----
    STAGE_X(0); CP_COMMIT();
    STAGE_X(1); CP_COMMIT();
    CP_WAIT1();                 // X(0) done
    BAR_C(c);                   // X(0) visible chain-wide
    float wx_cur;
    WX_COMPUTE(0, wx_cur);
    float h_last = 0.0f;

    // stagger: chain B waits until chain A finishes step 0 (anti-phase seed)
    if (c == 1) BAR_ALL();

    for (int s = 0; s < SEQ; s++) {
        // 1. prefetch X(s+2); X(s+1) complete (this thread)
        if (s + 2 < SEQ) STAGE_X(s + 2);
        CP_COMMIT();
        CP_WAIT1();
        BAR_C(c);               // X(s+1) visible; hsh consumed; h(s) writers done (prev iter)

        // 2. overlap: chain-warp0 polls h(s) flags WHILE others compute wx(s+1)
        if (s > 0 && wc == 0) {
            const unsigned tgt = base + (unsigned)s;
            unsigned v = tgt;
            if (lane < 16) v = ldacq(fgrp + lane);
            while (__any_sync(0xffffffffu, (int)(v - tgt) < 0)) {
                if (lane < 16 && (int)(v - tgt) < 0) v = ldacq(fgrp + lane);
            }
        }
        float wx_next = 0.0f;
        if (s + 1 < SEQ) WX_COMPUTE(s + 1, wx_next);
        BAR_C(c);               // poll done + wx done

        // 3. stage h(s) into chain smem (8KB; 256 thr x 2 f4)
        if (s > 0) {
            const float* hsrc = g_hbuf + (s & 1) * (BATCH * HID) + (size_t)b0 * HID;
            float4 hv0 = ((const float4*)hsrc)[tc];
            float4 hv1 = ((const float4*)hsrc)[tc + 256];
            ((float4*)hshc)[tc]       = hv0;
            ((float4*)hshc)[tc + 256] = hv1;
        } else {
            ((float4*)hshc)[tc]       = make_float4(0.f, 0.f, 0.f, 0.f);
            ((float4*)hshc)[tc + 256] = make_float4(0.f, 0.f, 0.f, 0.f);
        }
        BAR_C(c);               // hsh ready

        // 4. scan compute: 4b x 4j FFMA2 tile, U from registers
        unsigned long long acc[16];
#pragma unroll
        for (int o = 0; o < 16; o++) acc[o] = 0ull;
#pragma unroll
        for (int qi = 0; qi < 4; qi++) {
            const int kb = qi * 128 + lane * 4;
            ulonglong2 hq[4];
#pragma unroll
            for (int b = 0; b < 4; b++)
                hq[b] = *(const ulonglong2*)(hshc + b * HID + kb);
#pragma unroll
            for (int b = 0; b < 4; b++)
#pragma unroll
                for (int j = 0; j < 4; j++) {
                    fma2(acc[b * 4 + j], hq[b].x, ureg[qi][j].x);
                    fma2(acc[b * 4 + j], hq[b].y, ureg[qi][j].y);
                }
        }
        float v[16];
#pragma unroll
        for (int o = 0; o < 16; o++) v[o] = lo2(acc[o]) + hi2(acc[o]);
        BFLY16(v, lane);

        if (writer) {
            float hnew = tanhf(wx_cur + ubj + v[0]);
            h_last = hnew;
            g_hbuf[((s + 1) & 1) * (BATCH * HID) + (size_t)babs * HID + jabs] = hnew;
        }

        // 5. order h stores before release
        BAR_C(c);
        if (tc == 0) strel(fgrp + jg, base + (unsigned)s + 1u);

        wx_cur = wx_next;

        // one-time stagger release: A finished step 0 -> unleash B
        if (c == 0 && s == 0) BAR_ALL();
    }

    // ---- fused readout (per chain) ----
    if (writer) hshc[ob * JGR + wc * 4 + ojl] = h_last;   // final tile [4][32]
    BAR_C(c);
    if (wc == 0 && lane < 8) {
        const int b = lane >> 1, o = lane & 1;
        float pt = 0.0f;
#pragma unroll
        for (int j = 0; j < JGR; j++)
            pt += hshc[b * JGR + j] * Vw[(size_t)(j0 + j) * 2 + o];
        g_opart[(g * 16 + jg) * 8 + lane] = pt;
    }
    BAR_C(c);
    if (tc == 0) strel(fgrp + jg, base + (unsigned)SEQ + 1u);

    if (jg == 0) {
        if (wc == 0) {
            const unsigned tgt = base + (unsigned)SEQ + 1u;
            unsigned v2 = tgt;
            if (lane < 16) v2 = ldacq(fgrp + lane);
            while (__any_sync(0xffffffffu, (int)(v2 - tgt) < 0)) {
                if (lane < 16 && (int)(v2 - tgt) < 0) v2 = ldacq(fgrp + lane);
            }
        }
        BAR_C(c);
        if (wc == 0 && lane < 8) {
            const int b = lane >> 1, o = lane & 1;
            float ssum = Vb[o];
#pragma unroll
            for (int gg = 0; gg < 16; gg++)
                ssum += g_opart[(g * 16 + gg) * 8 + lane];
            out[(size_t)(b0 + b) * 2 + o] = 1.0f / (1.0f + expf(-ssum));
        }
    }
}

// =====================================================================
extern "C" void kernel_launch(void* const* d_in, const int* in_sizes, int n_in,
                              void* d_out, int out_size) {
    const float* x  = (const float*)d_in[0];
    const float* Ww = (const float*)d_in[1];
    const float* Wb = (const float*)d_in[2];
    const float* Uw = (const float*)d_in[3];
    const float* Ub = (const float*)d_in[4];
    const float* Vw = (const float*)d_in[5];
    const float* Vb = (const float*)d_in[6];
    float* out = (float*)d_out;

    fused_kernel<<<NCTA, THR>>>(x, Ww, Wb, Uw, Ub, Vw, Vb, out);
}